// round 13
// baseline (speedup 1.0000x reference)
#include <cuda_runtime.h>
#include <cstdint>

#define NN 50000
#define NE 800000
#define CIN 128
#define CH 64
#define NB 196      // ceil(NN/256)
#define GB_E4 782   // ceil(NE/1024): edge kernels, 4 edges/thread
#define KC2 16      // GEMM K-chunk (two k8 steps)
#define XP 40       // Xhl row stride (floats): 16k*2 + 8 pad; banks 8g+2t distinct
#define WP 136      // Whl row stride (floats): 64n*2 + 8 pad; banks 8t+2g distinct

// ---------------- scratch (no allocs allowed -> device globals) ----------------
__device__ int   g_cnt[NN];        // in-degree histogram; self-cleaned by k_off
__device__ int   g_off[NN];        // CSR segment start per node
__device__ int   g_end[NN];        // CSR segment end per node
__device__ int   g_cur[NN];        // reorder cursors
__device__ float g_dis[NN];        // rsqrt(deg+1)
__device__ int   g_eidx[NE];       // dst-grouped src indices (CSR adjacency)
__device__ int   g_total;          // atomic base counter (reset by k_deg block 0)
__device__ float g_h1[(size_t)NN * CH];   // dis[i] * (x @ W1)
__device__ float g_acc1[(size_t)NN * CH]; // layer-1 output (post-bias, pre-ReLU)
__device__ float g_h2[(size_t)NN * CH];   // dis[i] * (relu(acc1) @ W2)

// ---------------- tf32 helpers ----------------
__device__ __forceinline__ uint32_t to_tf32(float x) {
    uint32_t r;
    asm("cvt.rna.tf32.f32 %0, %1;" : "=r"(r) : "f"(x));
    return r;
}
// split x into hi (tf32) + lo (tf32 of exact residual), packed as float2
__device__ __forceinline__ float2 tf32_split2(float x) {
    float hi = __uint_as_float(to_tf32(x));
    float lo = __uint_as_float(to_tf32(x - hi));
    return make_float2(hi, lo);
}
__device__ __forceinline__ void mma_tf32(float c[4], const uint32_t a[4],
                                         const uint32_t b[2]) {
    asm volatile(
        "mma.sync.aligned.m16n8k8.row.col.f32.tf32.tf32.f32 "
        "{%0,%1,%2,%3}, {%4,%5,%6,%7}, {%8,%9}, {%0,%1,%2,%3};"
        : "+f"(c[0]), "+f"(c[1]), "+f"(c[2]), "+f"(c[3])
        : "r"(a[0]), "r"(a[1]), "r"(a[2]), "r"(a[3]), "r"(b[0]), "r"(b[1]));
}

// per-block int64-vs-int32 detection (reads 16 leading entries; L2-hot)
__device__ __forceinline__ int detect64(const void* idx) {
    const long long* p = (const long long*)idx;
    int ok = 1;
    for (int j = 0; j < 16; j++) {
        long long v = p[j];
        if (v < 0 || v >= NN) ok = 0;
    }
    return ok;
}

// ---------------- degree histogram: 4 edges/thread, vectorized ----------------
__global__ __launch_bounds__(256) void k_deg(const void* __restrict__ idx) {
    __shared__ int s64;
    const int t = threadIdx.x;
    if (t == 0) {
        s64 = detect64(idx);
        if (blockIdx.x == 0) g_total = 0;
    }
    __syncthreads();
    int e0 = (blockIdx.x * 256 + t) * 4;
    if (e0 >= NE) return;
    int d0, d1, d2, d3;
    if (s64) {
        const ulonglong2* pd = (const ulonglong2*)((const long long*)idx + NE + e0);
        ulonglong2 a = __ldg(pd), b = __ldg(pd + 1);
        d0 = (int)a.x; d1 = (int)a.y; d2 = (int)b.x; d3 = (int)b.y;
    } else {
        int4 dv = __ldg((const int4*)((const int*)idx + NE + e0));
        d0 = dv.x; d1 = dv.y; d2 = dv.z; d3 = dv.w;
    }
    atomicAdd(&g_cnt[d0], 1);
    atomicAdd(&g_cnt[d1], 1);
    atomicAdd(&g_cnt[d2], 1);
    atomicAdd(&g_cnt[d3], 1);
}

// ---------------- fused offsets: block scan + atomic block base ----------------
__global__ __launch_bounds__(256) void k_off() {
    __shared__ int sm[256];
    __shared__ int sbase;
    const int t = threadIdx.x;
    int i = blockIdx.x * 256 + t;
    int c = (i < NN) ? g_cnt[i] : 0;
    sm[t] = c;
    __syncthreads();
    for (int o = 1; o < 256; o <<= 1) {
        int u = (t >= o) ? sm[t - o] : 0;
        __syncthreads();
        sm[t] += u;
        __syncthreads();
    }
    if (t == 255) sbase = atomicAdd(&g_total, sm[255]);
    __syncthreads();
    int off = sbase + sm[t] - c;
    if (i < NN) {
        g_off[i] = off;
        g_end[i] = off + c;
        g_cur[i] = off;
        g_dis[i] = rsqrtf((float)(c + 1));
        g_cnt[i] = 0;
    }
}

// ---------------- reorder: 4 edges/thread, reads edge_index directly ----------------
__global__ __launch_bounds__(256) void k_reorder(const void* __restrict__ idx) {
    __shared__ int s64;
    const int t = threadIdx.x;
    if (t == 0) s64 = detect64(idx);
    __syncthreads();
    int e0 = (blockIdx.x * 256 + t) * 4;
    if (e0 >= NE) return;
    int s0, s1, s2, s3, d0, d1, d2, d3;
    if (s64) {
        const long long* p = (const long long*)idx;
        ulonglong2 a = __ldg((const ulonglong2*)(p + e0));
        ulonglong2 b = __ldg((const ulonglong2*)(p + e0) + 1);
        ulonglong2 c = __ldg((const ulonglong2*)(p + NE + e0));
        ulonglong2 d = __ldg((const ulonglong2*)(p + NE + e0) + 1);
        s0 = (int)a.x; s1 = (int)a.y; s2 = (int)b.x; s3 = (int)b.y;
        d0 = (int)c.x; d1 = (int)c.y; d2 = (int)d.x; d3 = (int)d.y;
    } else {
        const int* p = (const int*)idx;
        int4 a = __ldg((const int4*)(p + e0));
        int4 c = __ldg((const int4*)(p + NE + e0));
        s0 = a.x; s1 = a.y; s2 = a.z; s3 = a.w;
        d0 = c.x; d1 = c.y; d2 = c.z; d3 = c.w;
    }
    int p0 = atomicAdd(&g_cur[d0], 1);
    int p1 = atomicAdd(&g_cur[d1], 1);
    int p2 = atomicAdd(&g_cur[d2], 1);
    int p3 = atomicAdd(&g_cur[d3], 1);
    g_eidx[p0] = s0;
    g_eidx[p1] = s1;
    g_eidx[p2] = s2;
    g_eidx[p3] = s3;
}

// ---------------- tensor-core GEMM body (3xtf32, hi/lo interleaved smem) ----------------
// Block 128(M)x64(N), 256 thr = 8 warps 4(M)x2(N); warp tile 32x32 (2 m16 x 4 n8).
// Smem packs (hi,lo) adjacent: every fragment element is one LDS.64.
// IN==1: read x (row stride CIN); IN==2: read relu(g_acc1) (row stride CH).
template <int KTOT, int IN>
__device__ __forceinline__ void gemm_tc(const float* __restrict__ xin,
                                        const float* __restrict__ W,
                                        float* __restrict__ hout) {
    __shared__ float Xhl[128 * XP];   // 20.5 KB: [row][k*2 + {hi,lo}]
    __shared__ float Whl[KC2 * WP];   // 8.7 KB:  [k][n*2 + {hi,lo}]
    const int t = threadIdx.x;
    const int row0 = blockIdx.x * 128;
    const int lane = t & 31;
    const int g = lane >> 2;     // 0..7
    const int tig = lane & 3;    // 0..3
    const int warp = t >> 5;
    const int m0w = (warp & 3) * 32;
    const int n0w = (warp >> 2) * 32;
    const int instr = (IN == 1) ? CIN : CH;

    float acc[2][4][4];
    #pragma unroll
    for (int mt = 0; mt < 2; mt++)
        #pragma unroll
        for (int nt = 0; nt < 4; nt++)
            #pragma unroll
            for (int q = 0; q < 4; q++) acc[mt][nt][q] = 0.0f;

    for (int kc = 0; kc < KTOT; kc += KC2) {
        __syncthreads();
        {   // W chunk: 16 k-rows x 64 n = 256 float4, 1 per thread
            int k = t >> 4, c4 = t & 15;
            float4 v = __ldg((const float4*)(W + (size_t)(kc + k) * CH) + c4);
            float2 sx = tf32_split2(v.x), sy = tf32_split2(v.y);
            float2 sz = tf32_split2(v.z), sw = tf32_split2(v.w);
            float* p = Whl + k * WP + c4 * 8;  // n = c4*4.. -> word n*2, 32B aligned
            *(float4*)p = make_float4(sx.x, sx.y, sy.x, sy.y);
            *(float4*)(p + 4) = make_float4(sz.x, sz.y, sw.x, sw.y);
        }
        #pragma unroll
        for (int i = 0; i < 2; i++) {  // X chunk: 128 rows x 16 k = 512 float4
            int fid = i * 256 + t;
            int row = fid >> 2, c4 = fid & 3;
            int gr = row0 + row;
            float4 v = make_float4(0.f, 0.f, 0.f, 0.f);
            if (gr < NN) {
                v = __ldg((const float4*)(xin + (size_t)gr * instr + kc) + c4);
                if (IN == 2) {
                    v.x = fmaxf(v.x, 0.f); v.y = fmaxf(v.y, 0.f);
                    v.z = fmaxf(v.z, 0.f); v.w = fmaxf(v.w, 0.f);
                }
            }
            float2 sx = tf32_split2(v.x), sy = tf32_split2(v.y);
            float2 sz = tf32_split2(v.z), sw = tf32_split2(v.w);
            float* p = Xhl + row * XP + c4 * 8;  // k = c4*4.. -> word k*2, 32B aligned
            *(float4*)p = make_float4(sx.x, sx.y, sy.x, sy.y);
            *(float4*)(p + 4) = make_float4(sz.x, sz.y, sw.x, sw.y);
        }
        __syncthreads();

        #pragma unroll
        for (int ks = 0; ks < KC2; ks += 8) {
            uint32_t bh[4][2], bl[4][2];
            #pragma unroll
            for (int nt = 0; nt < 4; nt++) {
                int n = n0w + nt * 8 + g;
                float2 b0 = *(const float2*)(Whl + (ks + tig) * WP + n * 2);
                float2 b1 = *(const float2*)(Whl + (ks + tig + 4) * WP + n * 2);
                bh[nt][0] = __float_as_uint(b0.x);
                bh[nt][1] = __float_as_uint(b1.x);
                bl[nt][0] = __float_as_uint(b0.y);
                bl[nt][1] = __float_as_uint(b1.y);
            }
            #pragma unroll
            for (int mt = 0; mt < 2; mt++) {
                int r0 = (m0w + mt * 16 + g) * XP;
                int r1 = (m0w + mt * 16 + g + 8) * XP;
                float2 a0 = *(const float2*)(Xhl + r0 + (ks + tig) * 2);
                float2 a1 = *(const float2*)(Xhl + r1 + (ks + tig) * 2);
                float2 a2 = *(const float2*)(Xhl + r0 + (ks + tig + 4) * 2);
                float2 a3 = *(const float2*)(Xhl + r1 + (ks + tig + 4) * 2);
                uint32_t ah[4] = {__float_as_uint(a0.x), __float_as_uint(a1.x),
                                  __float_as_uint(a2.x), __float_as_uint(a3.x)};
                uint32_t al[4] = {__float_as_uint(a0.y), __float_as_uint(a1.y),
                                  __float_as_uint(a2.y), __float_as_uint(a3.y)};
                #pragma unroll
                for (int nt = 0; nt < 4; nt++) {
                    mma_tf32(acc[mt][nt], ah, bh[nt]);  // hi*hi
                    mma_tf32(acc[mt][nt], ah, bl[nt]);  // hi*lo
                    mma_tf32(acc[mt][nt], al, bh[nt]);  // lo*hi
                }
            }
        }
    }

    // epilogue: hout[row] = dis[row] * acc
    #pragma unroll
    for (int mt = 0; mt < 2; mt++) {
        int ra = row0 + m0w + mt * 16 + g;
        int rb = ra + 8;
        float da = (ra < NN) ? g_dis[ra] : 0.f;
        float db = (rb < NN) ? g_dis[rb] : 0.f;
        #pragma unroll
        for (int nt = 0; nt < 4; nt++) {
            int col = n0w + nt * 8 + tig * 2;
            if (ra < NN) {
                float2 o = make_float2(acc[mt][nt][0] * da, acc[mt][nt][1] * da);
                *(float2*)(hout + (size_t)ra * CH + col) = o;
            }
            if (rb < NN) {
                float2 o = make_float2(acc[mt][nt][2] * db, acc[mt][nt][3] * db);
                *(float2*)(hout + (size_t)rb * CH + col) = o;
            }
        }
    }
}

__global__ __launch_bounds__(256) void k_gemm1(const float* __restrict__ x,
                                               const float* __restrict__ W) {
    gemm_tc<CIN, 1>(x, W, g_h1);
}
__global__ __launch_bounds__(256) void k_gemm2(const float* __restrict__ W) {
    gemm_tc<CH, 2>(g_acc1, W, g_h2);
}

// ---------------- CSR gather: dst[i] = dis[i]*(hs[i] + sum_e hs[src_e]) + b ----------------
template <int L>
__global__ __launch_bounds__(256) void k_gather(const float* __restrict__ b,
                                                float* __restrict__ out_arg) {
    const int node = blockIdx.x * 8 + (threadIdx.x >> 5);
    const int lane = threadIdx.x & 31;
    if (node >= NN) return;
    const float* __restrict__ hs = (L == 1) ? g_h1 : g_h2;
    float* __restrict__ dst = (L == 1) ? g_acc1 : out_arg;

    float2 acc = __ldg((const float2*)(hs + (size_t)node * CH) + lane);  // self term

    int e = g_off[node];
    const int s1 = g_end[node];
    for (; e + 4 <= s1; e += 4) {
        int sj0 = __ldg(g_eidx + e);
        int sj1 = __ldg(g_eidx + e + 1);
        int sj2 = __ldg(g_eidx + e + 2);
        int sj3 = __ldg(g_eidx + e + 3);
        float2 v0 = __ldg((const float2*)(hs + (size_t)sj0 * CH) + lane);
        float2 v1 = __ldg((const float2*)(hs + (size_t)sj1 * CH) + lane);
        float2 v2 = __ldg((const float2*)(hs + (size_t)sj2 * CH) + lane);
        float2 v3 = __ldg((const float2*)(hs + (size_t)sj3 * CH) + lane);
        acc.x += v0.x + v1.x + v2.x + v3.x;
        acc.y += v0.y + v1.y + v2.y + v3.y;
    }
    for (; e < s1; e++) {
        int sj = __ldg(g_eidx + e);
        float2 v = __ldg((const float2*)(hs + (size_t)sj * CH) + lane);
        acc.x += v.x;
        acc.y += v.y;
    }

    float ds = g_dis[node];
    float2 bv = __ldg((const float2*)b + lane);
    float2 o;
    o.x = ds * acc.x + bv.x;
    o.y = ds * acc.y + bv.y;
    *((float2*)(dst + (size_t)node * CH) + lane) = o;
}

// ---------------- launch ----------------
extern "C" void kernel_launch(void* const* d_in, const int* in_sizes, int n_in,
                              void* d_out, int out_size) {
    const float* x  = (const float*)d_in[0];
    const void*  ei = d_in[1];
    const float* W1 = (const float*)d_in[2];
    const float* b1 = (const float*)d_in[3];
    const float* W2 = (const float*)d_in[4];
    const float* b2 = (const float*)d_in[5];
    float* out = (float*)d_out;

    k_deg<<<GB_E4, 256>>>(ei);
    k_off<<<NB, 256>>>();
    k_reorder<<<GB_E4, 256>>>(ei);
    k_gemm1<<<(NN + 127) / 128, 256>>>(x, W1);
    k_gather<1><<<(NN + 7) / 8, 256>>>(b1, nullptr);
    k_gemm2<<<(NN + 127) / 128, 256>>>(W2);
    k_gather<2><<<(NN + 7) / 8, 256>>>(b2, out);
}

// round 15
// speedup vs baseline: 1.0189x; 1.0189x over previous
#include <cuda_runtime.h>
#include <cstdint>

#define NN 50000
#define NE 800000
#define CIN 128
#define CH 64
#define NB 196      // ceil(NN/256)
#define GB_E4 782   // ceil(NE/1024): edge kernels, 4 edges/thread
#define KC2 16      // GEMM K-chunk (two k8 steps)
#define XP 40       // Xhl row stride (floats)
#define WP 136      // Whl row stride (floats)
#define XBUF (128 * XP)            // 5120 floats per X stage
#define WBUF (KC2 * WP)            // 2176 floats per W stage
#define GSMEM ((2 * XBUF + 2 * WBUF) * 4)  // 58368 B dynamic smem

// ---------------- scratch (no allocs allowed -> device globals) ----------------
__device__ int   g_cnt[NN];
__device__ int   g_off[NN];
__device__ int   g_end[NN];
__device__ int   g_cur[NN];
__device__ float g_dis[NN];
__device__ int   g_eidx[NE];
__device__ int   g_total;
__device__ float g_w1s[CIN * CH * 2];     // W1 pre-split, [k][n*2+{hi,lo}]
__device__ float g_w2s[CH * CH * 2];      // W2 pre-split
__device__ float g_h1[(size_t)NN * CH];
__device__ float g_acc1[(size_t)NN * CH];
__device__ float g_h2[(size_t)NN * CH];

// ---------------- tf32 helpers ----------------
__device__ __forceinline__ uint32_t to_tf32(float x) {
    uint32_t r;
    asm("cvt.rna.tf32.f32 %0, %1;" : "=r"(r) : "f"(x));
    return r;
}
__device__ __forceinline__ float2 tf32_split2(float x) {
    float hi = __uint_as_float(to_tf32(x));
    float lo = __uint_as_float(to_tf32(x - hi));
    return make_float2(hi, lo);
}
__device__ __forceinline__ void mma_tf32(float c[4], const uint32_t a[4],
                                         const uint32_t b[2]) {
    asm volatile(
        "mma.sync.aligned.m16n8k8.row.col.f32.tf32.tf32.f32 "
        "{%0,%1,%2,%3}, {%4,%5,%6,%7}, {%8,%9}, {%0,%1,%2,%3};"
        : "+f"(c[0]), "+f"(c[1]), "+f"(c[2]), "+f"(c[3])
        : "r"(a[0]), "r"(a[1]), "r"(a[2]), "r"(a[3]), "r"(b[0]), "r"(b[1]));
}

__device__ __forceinline__ int detect64(const void* idx) {
    const long long* p = (const long long*)idx;
    int ok = 1;
    for (int j = 0; j < 16; j++) {
        long long v = p[j];
        if (v < 0 || v >= NN) ok = 0;
    }
    return ok;
}

// ---------------- weight pre-split (once per call) ----------------
__global__ __launch_bounds__(256) void k_wsplit(const float* __restrict__ W1,
                                                const float* __restrict__ W2) {
    int i = blockIdx.x * 256 + threadIdx.x;
    if (i < CIN * CH) {
        float2 s = tf32_split2(__ldg(W1 + i));
        int k = i >> 6, n = i & 63;
        g_w1s[k * 128 + n * 2] = s.x;
        g_w1s[k * 128 + n * 2 + 1] = s.y;
    } else if (i < CIN * CH + CH * CH) {
        int j = i - CIN * CH;
        float2 s = tf32_split2(__ldg(W2 + j));
        int k = j >> 6, n = j & 63;
        g_w2s[k * 128 + n * 2] = s.x;
        g_w2s[k * 128 + n * 2 + 1] = s.y;
    }
}

// ---------------- degree histogram: 4 edges/thread, vectorized ----------------
__global__ __launch_bounds__(256) void k_deg(const void* __restrict__ idx) {
    __shared__ int s64;
    const int t = threadIdx.x;
    if (t == 0) {
        s64 = detect64(idx);
        if (blockIdx.x == 0) g_total = 0;
    }
    __syncthreads();
    int e0 = (blockIdx.x * 256 + t) * 4;
    if (e0 >= NE) return;
    int d0, d1, d2, d3;
    if (s64) {
        const ulonglong2* pd = (const ulonglong2*)((const long long*)idx + NE + e0);
        ulonglong2 a = __ldg(pd), b = __ldg(pd + 1);
        d0 = (int)a.x; d1 = (int)a.y; d2 = (int)b.x; d3 = (int)b.y;
    } else {
        int4 dv = __ldg((const int4*)((const int*)idx + NE + e0));
        d0 = dv.x; d1 = dv.y; d2 = dv.z; d3 = dv.w;
    }
    atomicAdd(&g_cnt[d0], 1);
    atomicAdd(&g_cnt[d1], 1);
    atomicAdd(&g_cnt[d2], 1);
    atomicAdd(&g_cnt[d3], 1);
}

// ---------------- fused offsets: block scan + atomic block base ----------------
__global__ __launch_bounds__(256) void k_off() {
    __shared__ int sm[256];
    __shared__ int sbase;
    const int t = threadIdx.x;
    int i = blockIdx.x * 256 + t;
    int c = (i < NN) ? g_cnt[i] : 0;
    sm[t] = c;
    __syncthreads();
    for (int o = 1; o < 256; o <<= 1) {
        int u = (t >= o) ? sm[t - o] : 0;
        __syncthreads();
        sm[t] += u;
        __syncthreads();
    }
    if (t == 255) sbase = atomicAdd(&g_total, sm[255]);
    __syncthreads();
    int off = sbase + sm[t] - c;
    if (i < NN) {
        g_off[i] = off;
        g_end[i] = off + c;
        g_cur[i] = off;
        g_dis[i] = rsqrtf((float)(c + 1));
        g_cnt[i] = 0;
    }
}

// ---------------- reorder: 4 edges/thread ----------------
__global__ __launch_bounds__(256) void k_reorder(const void* __restrict__ idx) {
    __shared__ int s64;
    const int t = threadIdx.x;
    if (t == 0) s64 = detect64(idx);
    __syncthreads();
    int e0 = (blockIdx.x * 256 + t) * 4;
    if (e0 >= NE) return;
    int s0, s1, s2, s3, d0, d1, d2, d3;
    if (s64) {
        const long long* p = (const long long*)idx;
        ulonglong2 a = __ldg((const ulonglong2*)(p + e0));
        ulonglong2 b = __ldg((const ulonglong2*)(p + e0) + 1);
        ulonglong2 c = __ldg((const ulonglong2*)(p + NE + e0));
        ulonglong2 d = __ldg((const ulonglong2*)(p + NE + e0) + 1);
        s0 = (int)a.x; s1 = (int)a.y; s2 = (int)b.x; s3 = (int)b.y;
        d0 = (int)c.x; d1 = (int)c.y; d2 = (int)d.x; d3 = (int)d.y;
    } else {
        const int* p = (const int*)idx;
        int4 a = __ldg((const int4*)(p + e0));
        int4 c = __ldg((const int4*)(p + NE + e0));
        s0 = a.x; s1 = a.y; s2 = a.z; s3 = a.w;
        d0 = c.x; d1 = c.y; d2 = c.z; d3 = c.w;
    }
    int p0 = atomicAdd(&g_cur[d0], 1);
    int p1 = atomicAdd(&g_cur[d1], 1);
    int p2 = atomicAdd(&g_cur[d2], 1);
    int p3 = atomicAdd(&g_cur[d3], 1);
    g_eidx[p0] = s0;
    g_eidx[p1] = s1;
    g_eidx[p2] = s2;
    g_eidx[p3] = s3;
}

// ---------------- tensor-core GEMM (3xtf32, double-buffered, dynamic smem) ----------------
// Block 128(M)x64(N), 256 thr = 8 warps 4(M)x2(N); warp tile 32x32 (2 m16 x 4 n8).
// While computing chunk c from buf[c%2], regs hold chunk c+1; after compute:
// split+STS c+1 -> buf[(c+1)%2], LDG c+2, 1 sync.
template <int KTOT, int IN>
__device__ __forceinline__ void gemm_tc(const float* __restrict__ xin,
                                        const float* __restrict__ wsplit,
                                        float* __restrict__ hout) {
    constexpr int NCH = KTOT / KC2;
    extern __shared__ float smem[];
    float* Xb0 = smem;                 // [2][XBUF]
    float* Wb0 = smem + 2 * XBUF;      // [2][WBUF]
    const int t = threadIdx.x;
    const int row0 = blockIdx.x * 128;
    const int lane = t & 31;
    const int g = lane >> 2;
    const int tig = lane & 3;
    const int warp = t >> 5;
    const int m0w = (warp & 3) * 32;
    const int n0w = (warp >> 2) * 32;
    const int instr = (IN == 1) ? CIN : CH;

    const int xrow = t >> 2;   // X rows xrow and xrow+64
    const int xc4 = t & 3;
    const int wk = t >> 4;
    const int wc = t & 15;

    float4 xr0, xr1, wr0, wr1;  // staged chunk

    auto ldg_chunk = [&](int kc) {
        int gr0 = row0 + xrow;
        int gr1 = row0 + 64 + xrow;
        xr0 = make_float4(0.f, 0.f, 0.f, 0.f);
        xr1 = make_float4(0.f, 0.f, 0.f, 0.f);
        if (gr0 < NN) {
            xr0 = __ldg((const float4*)(xin + (size_t)gr0 * instr + kc) + xc4);
            if (IN == 2) {
                xr0.x = fmaxf(xr0.x, 0.f); xr0.y = fmaxf(xr0.y, 0.f);
                xr0.z = fmaxf(xr0.z, 0.f); xr0.w = fmaxf(xr0.w, 0.f);
            }
        }
        if (gr1 < NN) {
            xr1 = __ldg((const float4*)(xin + (size_t)gr1 * instr + kc) + xc4);
            if (IN == 2) {
                xr1.x = fmaxf(xr1.x, 0.f); xr1.y = fmaxf(xr1.y, 0.f);
                xr1.z = fmaxf(xr1.z, 0.f); xr1.w = fmaxf(xr1.w, 0.f);
            }
        }
        const float4* wp = (const float4*)wsplit + (size_t)(kc + wk) * 32 + wc * 2;
        wr0 = __ldg(wp);
        wr1 = __ldg(wp + 1);
    };

    auto sts_chunk = [&](int b) {
        float* Xb = Xb0 + b * XBUF;
        float* Wb = Wb0 + b * WBUF;
        float2 s0 = tf32_split2(xr0.x), s1 = tf32_split2(xr0.y);
        float2 s2 = tf32_split2(xr0.z), s3 = tf32_split2(xr0.w);
        float* p = Xb + xrow * XP + xc4 * 8;
        *(float4*)p = make_float4(s0.x, s0.y, s1.x, s1.y);
        *(float4*)(p + 4) = make_float4(s2.x, s2.y, s3.x, s3.y);
        s0 = tf32_split2(xr1.x); s1 = tf32_split2(xr1.y);
        s2 = tf32_split2(xr1.z); s3 = tf32_split2(xr1.w);
        p = Xb + (64 + xrow) * XP + xc4 * 8;
        *(float4*)p = make_float4(s0.x, s0.y, s1.x, s1.y);
        *(float4*)(p + 4) = make_float4(s2.x, s2.y, s3.x, s3.y);
        float* q = Wb + wk * WP + wc * 8;
        *(float4*)q = wr0;
        *(float4*)(q + 4) = wr1;
    };

    float acc[2][4][4];
    #pragma unroll
    for (int mt = 0; mt < 2; mt++)
        #pragma unroll
        for (int nt = 0; nt < 4; nt++)
            #pragma unroll
            for (int q = 0; q < 4; q++) acc[mt][nt][q] = 0.0f;

    auto compute = [&](int b) {
        const float* Xb = Xb0 + b * XBUF;
        const float* Wb = Wb0 + b * WBUF;
        #pragma unroll
        for (int ks = 0; ks < KC2; ks += 8) {
            uint32_t bh[4][2], bl[4][2];
            #pragma unroll
            for (int nt = 0; nt < 4; nt++) {
                int n = n0w + nt * 8 + g;
                float2 b0 = *(const float2*)(Wb + (ks + tig) * WP + n * 2);
                float2 b1 = *(const float2*)(Wb + (ks + tig + 4) * WP + n * 2);
                bh[nt][0] = __float_as_uint(b0.x);
                bh[nt][1] = __float_as_uint(b1.x);
                bl[nt][0] = __float_as_uint(b0.y);
                bl[nt][1] = __float_as_uint(b1.y);
            }
            #pragma unroll
            for (int mt = 0; mt < 2; mt++) {
                int r0 = (m0w + mt * 16 + g) * XP;
                int r1 = (m0w + mt * 16 + g + 8) * XP;
                float2 a0 = *(const float2*)(Xb + r0 + (ks + tig) * 2);
                float2 a1 = *(const float2*)(Xb + r1 + (ks + tig) * 2);
                float2 a2 = *(const float2*)(Xb + r0 + (ks + tig + 4) * 2);
                float2 a3 = *(const float2*)(Xb + r1 + (ks + tig + 4) * 2);
                uint32_t ah[4] = {__float_as_uint(a0.x), __float_as_uint(a1.x),
                                  __float_as_uint(a2.x), __float_as_uint(a3.x)};
                uint32_t al[4] = {__float_as_uint(a0.y), __float_as_uint(a1.y),
                                  __float_as_uint(a2.y), __float_as_uint(a3.y)};
                #pragma unroll
                for (int nt = 0; nt < 4; nt++) {
                    mma_tf32(acc[mt][nt], ah, bh[nt]);
                    mma_tf32(acc[mt][nt], ah, bl[nt]);
                    mma_tf32(acc[mt][nt], al, bh[nt]);
                }
            }
        }
    };

    // pipeline
    ldg_chunk(0);
    sts_chunk(0);
    if (NCH > 1) ldg_chunk(KC2);
    __syncthreads();
    for (int c = 0; c < NCH; c++) {
        compute(c & 1);
        if (c + 1 < NCH) {
            sts_chunk((c + 1) & 1);
            if (c + 2 < NCH) ldg_chunk((c + 2) * KC2);
            __syncthreads();
        }
    }

    // epilogue: hout[row] = dis[row] * acc
    #pragma unroll
    for (int mt = 0; mt < 2; mt++) {
        int ra = row0 + m0w + mt * 16 + g;
        int rb = ra + 8;
        float da = (ra < NN) ? g_dis[ra] : 0.f;
        float db = (rb < NN) ? g_dis[rb] : 0.f;
        #pragma unroll
        for (int nt = 0; nt < 4; nt++) {
            int col = n0w + nt * 8 + tig * 2;
            if (ra < NN) {
                float2 o = make_float2(acc[mt][nt][0] * da, acc[mt][nt][1] * da);
                *(float2*)(hout + (size_t)ra * CH + col) = o;
            }
            if (rb < NN) {
                float2 o = make_float2(acc[mt][nt][2] * db, acc[mt][nt][3] * db);
                *(float2*)(hout + (size_t)rb * CH + col) = o;
            }
        }
    }
}

__global__ __launch_bounds__(256) void k_gemm1(const float* __restrict__ x) {
    gemm_tc<CIN, 1>(x, g_w1s, g_h1);
}
__global__ __launch_bounds__(256) void k_gemm2() {
    gemm_tc<CH, 2>(g_acc1, g_w2s, g_h2);
}

// ---------------- CSR gather: dst[i] = dis[i]*(hs[i] + sum_e hs[src_e]) + b ----------------
template <int L>
__global__ __launch_bounds__(256) void k_gather(const float* __restrict__ b,
                                                float* __restrict__ out_arg) {
    const int node = blockIdx.x * 8 + (threadIdx.x >> 5);
    const int lane = threadIdx.x & 31;
    if (node >= NN) return;
    const float* __restrict__ hs = (L == 1) ? g_h1 : g_h2;
    float* __restrict__ dst = (L == 1) ? g_acc1 : out_arg;

    float2 acc = __ldg((const float2*)(hs + (size_t)node * CH) + lane);

    int e = g_off[node];
    const int s1 = g_end[node];
    for (; e + 4 <= s1; e += 4) {
        int sj0 = __ldg(g_eidx + e);
        int sj1 = __ldg(g_eidx + e + 1);
        int sj2 = __ldg(g_eidx + e + 2);
        int sj3 = __ldg(g_eidx + e + 3);
        float2 v0 = __ldg((const float2*)(hs + (size_t)sj0 * CH) + lane);
        float2 v1 = __ldg((const float2*)(hs + (size_t)sj1 * CH) + lane);
        float2 v2 = __ldg((const float2*)(hs + (size_t)sj2 * CH) + lane);
        float2 v3 = __ldg((const float2*)(hs + (size_t)sj3 * CH) + lane);
        acc.x += v0.x + v1.x + v2.x + v3.x;
        acc.y += v0.y + v1.y + v2.y + v3.y;
    }
    for (; e < s1; e++) {
        int sj = __ldg(g_eidx + e);
        float2 v = __ldg((const float2*)(hs + (size_t)sj * CH) + lane);
        acc.x += v.x;
        acc.y += v.y;
    }

    float ds = g_dis[node];
    float2 bv = __ldg((const float2*)b + lane);
    float2 o;
    o.x = ds * acc.x + bv.x;
    o.y = ds * acc.y + bv.y;
    *((float2*)(dst + (size_t)node * CH) + lane) = o;
}

// ---------------- launch ----------------
extern "C" void kernel_launch(void* const* d_in, const int* in_sizes, int n_in,
                              void* d_out, int out_size) {
    const float* x  = (const float*)d_in[0];
    const void*  ei = d_in[1];
    const float* W1 = (const float*)d_in[2];
    const float* b1 = (const float*)d_in[3];
    const float* W2 = (const float*)d_in[4];
    const float* b2 = (const float*)d_in[5];
    float* out = (float*)d_out;

    cudaFuncSetAttribute(k_gemm1, cudaFuncAttributeMaxDynamicSharedMemorySize,
                         GSMEM);
    cudaFuncSetAttribute(k_gemm2, cudaFuncAttributeMaxDynamicSharedMemorySize,
                         GSMEM);

    k_wsplit<<<48, 256>>>(W1, W2);
    k_deg<<<GB_E4, 256>>>(ei);
    k_off<<<NB, 256>>>();
    k_reorder<<<GB_E4, 256>>>(ei);
    k_gemm1<<<(NN + 127) / 128, 256, GSMEM>>>(x);
    k_gather<1><<<(NN + 7) / 8, 256>>>(b1, nullptr);
    k_gemm2<<<(NN + 127) / 128, 256, GSMEM>>>();
    k_gather<2><<<(NN + 7) / 8, 256>>>(b2, out);
}

// round 17
// speedup vs baseline: 1.0360x; 1.0168x over previous
#include <cuda_runtime.h>
#include <cstdint>

#define NN 50000
#define NE 800000
#define CIN 128
#define CH 64
#define NB 196      // ceil(NN/256)
#define GB_E4 782   // ceil(NE/1024): edge kernels, 4 edges/thread
#define KC2 16      // GEMM K-chunk (two k8 steps)
#define XP 40       // Xhl row stride (floats)
#define WP 136      // Whl row stride (floats)
#define XBUF (128 * XP)
#define WBUF (KC2 * WP)
#define GSMEM ((2 * XBUF + 2 * WBUF) * 4)  // 58368 B dynamic smem

// ---------------- scratch (no allocs allowed -> device globals) ----------------
__device__ int   g_cnt[NN];        // histogram; doubles as rank source; self-cleaned
__device__ int2  g_span[NN];       // {segment start, segment end}
__device__ float g_dis[NN];        // rsqrt(deg+1)
__device__ int   g_rank[NE];       // within-dst rank of each edge (from k_deg)
__device__ int   g_eidx[NE];       // dst-grouped src indices (CSR adjacency)
__device__ int   g_total;          // atomic base counter
__device__ float g_w1s[CIN * CH * 2];     // W1 pre-split, [k][n*2+{hi,lo}]
__device__ float g_w2s[CH * CH * 2];      // W2 pre-split
__device__ float g_h1[(size_t)NN * CH];
__device__ float g_acc1[(size_t)NN * CH];
__device__ float g_h2[(size_t)NN * CH];

// ---------------- tf32 helpers ----------------
__device__ __forceinline__ uint32_t to_tf32(float x) {
    uint32_t r;
    asm("cvt.rna.tf32.f32 %0, %1;" : "=r"(r) : "f"(x));
    return r;
}
__device__ __forceinline__ float2 tf32_split2(float x) {
    float hi = __uint_as_float(to_tf32(x));
    float lo = __uint_as_float(to_tf32(x - hi));
    return make_float2(hi, lo);
}
__device__ __forceinline__ void mma_tf32(float c[4], const uint32_t a[4],
                                         const uint32_t b[2]) {
    asm volatile(
        "mma.sync.aligned.m16n8k8.row.col.f32.tf32.tf32.f32 "
        "{%0,%1,%2,%3}, {%4,%5,%6,%7}, {%8,%9}, {%0,%1,%2,%3};"
        : "+f"(c[0]), "+f"(c[1]), "+f"(c[2]), "+f"(c[3])
        : "r"(a[0]), "r"(a[1]), "r"(a[2]), "r"(a[3]), "r"(b[0]), "r"(b[1]));
}

__device__ __forceinline__ int detect64(const void* idx) {
    const long long* p = (const long long*)idx;
    int ok = 1;
    for (int j = 0; j < 16; j++) {
        long long v = p[j];
        if (v < 0 || v >= NN) ok = 0;
    }
    return ok;
}

// ---------------- weight pre-split (once per call) ----------------
__global__ __launch_bounds__(256) void k_wsplit(const float* __restrict__ W1,
                                                const float* __restrict__ W2) {
    int i = blockIdx.x * 256 + threadIdx.x;
    if (i < CIN * CH) {
        float2 s = tf32_split2(__ldg(W1 + i));
        int k = i >> 6, n = i & 63;
        g_w1s[k * 128 + n * 2] = s.x;
        g_w1s[k * 128 + n * 2 + 1] = s.y;
    } else if (i < CIN * CH + CH * CH) {
        int j = i - CIN * CH;
        float2 s = tf32_split2(__ldg(W2 + j));
        int k = j >> 6, n = j & 63;
        g_w2s[k * 128 + n * 2] = s.x;
        g_w2s[k * 128 + n * 2 + 1] = s.y;
    }
}

// ---------------- degree histogram + edge ranks: 4 edges/thread ----------------
// atomicAdd return value IS the edge's within-node rank -> stored for the
// atomic-free reorder pass.
__global__ __launch_bounds__(256) void k_deg(const void* __restrict__ idx) {
    __shared__ int s64;
    const int t = threadIdx.x;
    if (t == 0) {
        s64 = detect64(idx);
        if (blockIdx.x == 0) g_total = 0;
    }
    __syncthreads();
    int e0 = (blockIdx.x * 256 + t) * 4;
    if (e0 >= NE) return;
    int d0, d1, d2, d3;
    if (s64) {
        const ulonglong2* pd = (const ulonglong2*)((const long long*)idx + NE + e0);
        ulonglong2 a = __ldg(pd), b = __ldg(pd + 1);
        d0 = (int)a.x; d1 = (int)a.y; d2 = (int)b.x; d3 = (int)b.y;
    } else {
        int4 dv = __ldg((const int4*)((const int*)idx + NE + e0));
        d0 = dv.x; d1 = dv.y; d2 = dv.z; d3 = dv.w;
    }
    int4 r;
    r.x = atomicAdd(&g_cnt[d0], 1);
    r.y = atomicAdd(&g_cnt[d1], 1);
    r.z = atomicAdd(&g_cnt[d2], 1);
    r.w = atomicAdd(&g_cnt[d3], 1);
    *(int4*)(g_rank + e0) = r;
}

// ---------------- fused offsets: block scan + atomic block base ----------------
__global__ __launch_bounds__(256) void k_off() {
    __shared__ int sm[256];
    __shared__ int sbase;
    const int t = threadIdx.x;
    int i = blockIdx.x * 256 + t;
    int c = (i < NN) ? g_cnt[i] : 0;
    sm[t] = c;
    __syncthreads();
    for (int o = 1; o < 256; o <<= 1) {
        int u = (t >= o) ? sm[t - o] : 0;
        __syncthreads();
        sm[t] += u;
        __syncthreads();
    }
    if (t == 255) sbase = atomicAdd(&g_total, sm[255]);
    __syncthreads();
    int off = sbase + sm[t] - c;
    if (i < NN) {
        g_span[i] = make_int2(off, off + c);
        g_dis[i] = rsqrtf((float)(c + 1));  // degree includes self-loop
        g_cnt[i] = 0;                       // clean for next call
    }
}

// ---------------- reorder: ATOMIC-FREE, pos = span[d].x + rank[e] ----------------
__global__ __launch_bounds__(256) void k_reorder(const void* __restrict__ idx) {
    __shared__ int s64;
    const int t = threadIdx.x;
    if (t == 0) s64 = detect64(idx);
    __syncthreads();
    int e0 = (blockIdx.x * 256 + t) * 4;
    if (e0 >= NE) return;
    int s0, s1, s2, s3, d0, d1, d2, d3;
    if (s64) {
        const long long* p = (const long long*)idx;
        ulonglong2 a = __ldg((const ulonglong2*)(p + e0));
        ulonglong2 b = __ldg((const ulonglong2*)(p + e0) + 1);
        ulonglong2 c = __ldg((const ulonglong2*)(p + NE + e0));
        ulonglong2 d = __ldg((const ulonglong2*)(p + NE + e0) + 1);
        s0 = (int)a.x; s1 = (int)a.y; s2 = (int)b.x; s3 = (int)b.y;
        d0 = (int)c.x; d1 = (int)c.y; d2 = (int)d.x; d3 = (int)d.y;
    } else {
        const int* p = (const int*)idx;
        int4 a = __ldg((const int4*)(p + e0));
        int4 c = __ldg((const int4*)(p + NE + e0));
        s0 = a.x; s1 = a.y; s2 = a.z; s3 = a.w;
        d0 = c.x; d1 = c.y; d2 = c.z; d3 = c.w;
    }
    int4 r = __ldg((const int4*)(g_rank + e0));
    int p0 = __ldg(&g_span[d0].x) + r.x;
    int p1 = __ldg(&g_span[d1].x) + r.y;
    int p2 = __ldg(&g_span[d2].x) + r.z;
    int p3 = __ldg(&g_span[d3].x) + r.w;
    g_eidx[p0] = s0;
    g_eidx[p1] = s1;
    g_eidx[p2] = s2;
    g_eidx[p3] = s3;
}

// ---------------- tensor-core GEMM (3xtf32, double-buffered, dynamic smem) ----------------
template <int KTOT, int IN>
__device__ __forceinline__ void gemm_tc(const float* __restrict__ xin,
                                        const float* __restrict__ wsplit,
                                        float* __restrict__ hout) {
    constexpr int NCH = KTOT / KC2;
    extern __shared__ float smem[];
    float* Xb0 = smem;
    float* Wb0 = smem + 2 * XBUF;
    const int t = threadIdx.x;
    const int row0 = blockIdx.x * 128;
    const int lane = t & 31;
    const int g = lane >> 2;
    const int tig = lane & 3;
    const int warp = t >> 5;
    const int m0w = (warp & 3) * 32;
    const int n0w = (warp >> 2) * 32;
    const int instr = (IN == 1) ? CIN : CH;

    const int xrow = t >> 2;
    const int xc4 = t & 3;
    const int wk = t >> 4;
    const int wc = t & 15;

    float4 xr0, xr1, wr0, wr1;

    auto ldg_chunk = [&](int kc) {
        int gr0 = row0 + xrow;
        int gr1 = row0 + 64 + xrow;
        xr0 = make_float4(0.f, 0.f, 0.f, 0.f);
        xr1 = make_float4(0.f, 0.f, 0.f, 0.f);
        if (gr0 < NN) {
            xr0 = __ldg((const float4*)(xin + (size_t)gr0 * instr + kc) + xc4);
            if (IN == 2) {
                xr0.x = fmaxf(xr0.x, 0.f); xr0.y = fmaxf(xr0.y, 0.f);
                xr0.z = fmaxf(xr0.z, 0.f); xr0.w = fmaxf(xr0.w, 0.f);
            }
        }
        if (gr1 < NN) {
            xr1 = __ldg((const float4*)(xin + (size_t)gr1 * instr + kc) + xc4);
            if (IN == 2) {
                xr1.x = fmaxf(xr1.x, 0.f); xr1.y = fmaxf(xr1.y, 0.f);
                xr1.z = fmaxf(xr1.z, 0.f); xr1.w = fmaxf(xr1.w, 0.f);
            }
        }
        const float4* wp = (const float4*)wsplit + (size_t)(kc + wk) * 32 + wc * 2;
        wr0 = __ldg(wp);
        wr1 = __ldg(wp + 1);
    };

    auto sts_chunk = [&](int b) {
        float* Xb = Xb0 + b * XBUF;
        float* Wb = Wb0 + b * WBUF;
        float2 s0 = tf32_split2(xr0.x), s1 = tf32_split2(xr0.y);
        float2 s2 = tf32_split2(xr0.z), s3 = tf32_split2(xr0.w);
        float* p = Xb + xrow * XP + xc4 * 8;
        *(float4*)p = make_float4(s0.x, s0.y, s1.x, s1.y);
        *(float4*)(p + 4) = make_float4(s2.x, s2.y, s3.x, s3.y);
        s0 = tf32_split2(xr1.x); s1 = tf32_split2(xr1.y);
        s2 = tf32_split2(xr1.z); s3 = tf32_split2(xr1.w);
        p = Xb + (64 + xrow) * XP + xc4 * 8;
        *(float4*)p = make_float4(s0.x, s0.y, s1.x, s1.y);
        *(float4*)(p + 4) = make_float4(s2.x, s2.y, s3.x, s3.y);
        float* q = Wb + wk * WP + wc * 8;
        *(float4*)q = wr0;
        *(float4*)(q + 4) = wr1;
    };

    float acc[2][4][4];
    #pragma unroll
    for (int mt = 0; mt < 2; mt++)
        #pragma unroll
        for (int nt = 0; nt < 4; nt++)
            #pragma unroll
            for (int q = 0; q < 4; q++) acc[mt][nt][q] = 0.0f;

    auto compute = [&](int b) {
        const float* Xb = Xb0 + b * XBUF;
        const float* Wb = Wb0 + b * WBUF;
        #pragma unroll
        for (int ks = 0; ks < KC2; ks += 8) {
            uint32_t bh[4][2], bl[4][2];
            #pragma unroll
            for (int nt = 0; nt < 4; nt++) {
                int n = n0w + nt * 8 + g;
                float2 b0 = *(const float2*)(Wb + (ks + tig) * WP + n * 2);
                float2 b1 = *(const float2*)(Wb + (ks + tig + 4) * WP + n * 2);
                bh[nt][0] = __float_as_uint(b0.x);
                bh[nt][1] = __float_as_uint(b1.x);
                bl[nt][0] = __float_as_uint(b0.y);
                bl[nt][1] = __float_as_uint(b1.y);
            }
            #pragma unroll
            for (int mt = 0; mt < 2; mt++) {
                int r0 = (m0w + mt * 16 + g) * XP;
                int r1 = (m0w + mt * 16 + g + 8) * XP;
                float2 a0 = *(const float2*)(Xb + r0 + (ks + tig) * 2);
                float2 a1 = *(const float2*)(Xb + r1 + (ks + tig) * 2);
                float2 a2 = *(const float2*)(Xb + r0 + (ks + tig + 4) * 2);
                float2 a3 = *(const float2*)(Xb + r1 + (ks + tig + 4) * 2);
                uint32_t ah[4] = {__float_as_uint(a0.x), __float_as_uint(a1.x),
                                  __float_as_uint(a2.x), __float_as_uint(a3.x)};
                uint32_t al[4] = {__float_as_uint(a0.y), __float_as_uint(a1.y),
                                  __float_as_uint(a2.y), __float_as_uint(a3.y)};
                #pragma unroll
                for (int nt = 0; nt < 4; nt++) {
                    mma_tf32(acc[mt][nt], ah, bh[nt]);
                    mma_tf32(acc[mt][nt], ah, bl[nt]);
                    mma_tf32(acc[mt][nt], al, bh[nt]);
                }
            }
        }
    };

    ldg_chunk(0);
    sts_chunk(0);
    if (NCH > 1) ldg_chunk(KC2);
    __syncthreads();
    for (int c = 0; c < NCH; c++) {
        compute(c & 1);
        if (c + 1 < NCH) {
            sts_chunk((c + 1) & 1);
            if (c + 2 < NCH) ldg_chunk((c + 2) * KC2);
            __syncthreads();
        }
    }

    #pragma unroll
    for (int mt = 0; mt < 2; mt++) {
        int ra = row0 + m0w + mt * 16 + g;
        int rb = ra + 8;
        float da = (ra < NN) ? g_dis[ra] : 0.f;
        float db = (rb < NN) ? g_dis[rb] : 0.f;
        #pragma unroll
        for (int nt = 0; nt < 4; nt++) {
            int col = n0w + nt * 8 + tig * 2;
            if (ra < NN) {
                float2 o = make_float2(acc[mt][nt][0] * da, acc[mt][nt][1] * da);
                *(float2*)(hout + (size_t)ra * CH + col) = o;
            }
            if (rb < NN) {
                float2 o = make_float2(acc[mt][nt][2] * db, acc[mt][nt][3] * db);
                *(float2*)(hout + (size_t)rb * CH + col) = o;
            }
        }
    }
}

__global__ __launch_bounds__(256) void k_gemm1(const float* __restrict__ x) {
    gemm_tc<CIN, 1>(x, g_w1s, g_h1);
}
__global__ __launch_bounds__(256) void k_gemm2() {
    gemm_tc<CH, 2>(g_acc1, g_w2s, g_h2);
}

// ---------------- CSR gather: dst[i] = dis[i]*(hs[i] + sum_e hs[src_e]) + b ----------------
template <int L>
__global__ __launch_bounds__(256) void k_gather(const float* __restrict__ b,
                                                float* __restrict__ out_arg) {
    const int node = blockIdx.x * 8 + (threadIdx.x >> 5);
    const int lane = threadIdx.x & 31;
    if (node >= NN) return;
    const float* __restrict__ hs = (L == 1) ? g_h1 : g_h2;
    float* __restrict__ dst = (L == 1) ? g_acc1 : out_arg;

    int2 span = __ldg(g_span + node);
    float2 acc = __ldg((const float2*)(hs + (size_t)node * CH) + lane);

    int e = span.x;
    const int s1 = span.y;
    for (; e + 4 <= s1; e += 4) {
        int sj0 = __ldg(g_eidx + e);
        int sj1 = __ldg(g_eidx + e + 1);
        int sj2 = __ldg(g_eidx + e + 2);
        int sj3 = __ldg(g_eidx + e + 3);
        float2 v0 = __ldg((const float2*)(hs + (size_t)sj0 * CH) + lane);
        float2 v1 = __ldg((const float2*)(hs + (size_t)sj1 * CH) + lane);
        float2 v2 = __ldg((const float2*)(hs + (size_t)sj2 * CH) + lane);
        float2 v3 = __ldg((const float2*)(hs + (size_t)sj3 * CH) + lane);
        acc.x += v0.x + v1.x + v2.x + v3.x;
        acc.y += v0.y + v1.y + v2.y + v3.y;
    }
    for (; e < s1; e++) {
        int sj = __ldg(g_eidx + e);
        float2 v = __ldg((const float2*)(hs + (size_t)sj * CH) + lane);
        acc.x += v.x;
        acc.y += v.y;
    }

    float ds = g_dis[node];
    float2 bv = __ldg((const float2*)b + lane);
    float2 o;
    o.x = ds * acc.x + bv.x;
    o.y = ds * acc.y + bv.y;
    *((float2*)(dst + (size_t)node * CH) + lane) = o;
}

// ---------------- launch ----------------
extern "C" void kernel_launch(void* const* d_in, const int* in_sizes, int n_in,
                              void* d_out, int out_size) {
    const float* x  = (const float*)d_in[0];
    const void*  ei = d_in[1];
    const float* W1 = (const float*)d_in[2];
    const float* b1 = (const float*)d_in[3];
    const float* W2 = (const float*)d_in[4];
    const float* b2 = (const float*)d_in[5];
    float* out = (float*)d_out;

    cudaFuncSetAttribute(k_gemm1, cudaFuncAttributeMaxDynamicSharedMemorySize,
                         GSMEM);
    cudaFuncSetAttribute(k_gemm2, cudaFuncAttributeMaxDynamicSharedMemorySize,
                         GSMEM);

    k_wsplit<<<48, 256>>>(W1, W2);
    k_deg<<<GB_E4, 256>>>(ei);
    k_off<<<NB, 256>>>();
    k_reorder<<<GB_E4, 256>>>(ei);
    k_gemm1<<<(NN + 127) / 128, 256, GSMEM>>>(x);
    k_gather<1><<<(NN + 7) / 8, 256>>>(b1, nullptr);
    k_gemm2<<<(NN + 127) / 128, 256, GSMEM>>>();
    k_gather<2><<<(NN + 7) / 8, 256>>>(b2, out);
}